// round 11
// baseline (speedup 1.0000x reference)
#include <cuda_runtime.h>
#include <cuda_fp16.h>
#include <stdint.h>

#define IN_DIM 128
#define OUT_DIM 64
#define NH 4
#define DH 16
#define N_MAX 100000
#define E_MAX 1600000

#define HIST_BLOCKS 128
#define REORD_BLOCKS 128

#define KCH 32              // k-chunk
#define KP  36              // padded k stride (floats)

// ---------------- device scratch (no allocations allowed) ----------------
__device__ float  g_va[8 * IN_DIM];                   // rows 0-3 Wt*a_src, 4-7 Wt*a_dst
__device__ __half g_h16[(size_t)N_MAX * OUT_DIM];     // projected features (fp16)
__device__ float  g_ssrc[N_MAX * NH];
__device__ float  g_sdst[N_MAX * NH];
__device__ int    g_deg[N_MAX];
__device__ int    g_rowptr[N_MAX + 1];
__device__ int    g_wpos[N_MAX];
__device__ int    g_csr[E_MAX];
__device__ int    g_bsum[128];
__device__ int    g_boff[128];
__device__ int    g_count;
__device__ int    g_flag;

// ---------------- fast exp on FMA pipe ------------------------------------
__device__ __forceinline__ float fast_exp(float x) {
    float t = x * 1.4426950408889634f;
    float n = rintf(t);
    float u = t - n;
    float p = 1.33335581464e-3f;
    p = fmaf(p, u, 9.61812910763e-3f);
    p = fmaf(p, u, 5.55041086648e-2f);
    p = fmaf(p, u, 2.40226506959e-1f);
    p = fmaf(p, u, 6.93147180560e-1f);
    p = fmaf(p, u, 1.0f);
    int ni = (int)n;
    return __int_as_float(__float_as_int(p) + (ni << 23));
}

// ---------------- K_prep: va = W^T a, zero deg, reset scan sync ----------
__global__ void k_prep(const float* __restrict__ W,
                       const float* __restrict__ a_src,
                       const float* __restrict__ a_dst, int n) {
    int idx = blockIdx.x * blockDim.x + threadIdx.x;
    if (idx == 0) { g_count = 0; g_flag = 0; }
    if (idx < 1024) {
        int r = idx >> 7;          // 0..7
        int k = idx & 127;
        int hd = r & 3;
        const float* a = (r < 4) ? a_src : a_dst;
        float s = 0.f;
#pragma unroll
        for (int d = 0; d < DH; d++)
            s = fmaf(W[(hd * DH + d) * IN_DIM + k], a[hd * DH + d], s);
        g_va[r * IN_DIM + k] = s;
    } else if (idx - 1024 < n) {
        g_deg[idx - 1024] = 0;
    }
}

// ---------------- GEMM body: 128 rows x 80 cols, k-vectorized ------------
// Thread (tx,ty): rows ty*8..+7, h cols tx+16j (j=0..3), score col 64+tx.
// Inner loop loads float4 along k (LDS.128), 4 k-steps per load group.
__device__ __forceinline__ void gemm_body(const float* __restrict__ x,
                                          const float* __restrict__ W,
                                          int m0, int n) {
    __shared__ __align__(16) float xs[128][KP];   // [m][k-chunk]
    __shared__ __align__(16) float ws[80][KP];    // [col][k-chunk]

    const int t  = threadIdx.x;
    const int tx = t & 15;
    const int ty = t >> 4;

    float acc[8][5];
#pragma unroll
    for (int i = 0; i < 8; i++)
#pragma unroll
        for (int j = 0; j < 5; j++) acc[i][j] = 0.f;

    for (int kk = 0; kk < IN_DIM; kk += KCH) {
        // stage x: 128 rows x 8 float4 (1024 float4)
#pragma unroll
        for (int i = 0; i < 4; i++) {
            int idx = t + i * 256;
            int r = idx >> 3, c = idx & 7;
            float4 v = make_float4(0.f, 0.f, 0.f, 0.f);
            if (m0 + r < n)
                v = *(const float4*)&x[(size_t)(m0 + r) * IN_DIM + kk + c * 4];
            *(float4*)&xs[r][c * 4] = v;
        }
        // stage W|va|0: 80 rows x 8 float4 (640 float4)
#pragma unroll
        for (int i = 0; i < 3; i++) {
            int idx = t + i * 256;
            if (idx < 640) {
                int row = idx >> 3, c = idx & 7;
                float4 v = make_float4(0.f, 0.f, 0.f, 0.f);
                if (row < 64)      v = *(const float4*)&W[row * IN_DIM + kk + c * 4];
                else if (row < 72) v = *(const float4*)&g_va[(row - 64) * IN_DIM + kk + c * 4];
                *(float4*)&ws[row][c * 4] = v;
            }
        }
        __syncthreads();

#pragma unroll 2
        for (int k4 = 0; k4 < KCH; k4 += 4) {
            float4 wv[5];
#pragma unroll
            for (int j = 0; j < 4; j++)
                wv[j] = *(const float4*)&ws[tx + 16 * j][k4];
            wv[4] = *(const float4*)&ws[64 + tx][k4];
            float4 xv[8];
#pragma unroll
            for (int i = 0; i < 8; i++)
                xv[i] = *(const float4*)&xs[ty * 8 + i][k4];
#pragma unroll
            for (int i = 0; i < 8; i++)
#pragma unroll
                for (int j = 0; j < 5; j++) {
                    float a = acc[i][j];
                    a = fmaf(xv[i].x, wv[j].x, a);
                    a = fmaf(xv[i].y, wv[j].y, a);
                    a = fmaf(xv[i].z, wv[j].z, a);
                    a = fmaf(xv[i].w, wv[j].w, a);
                    acc[i][j] = a;
                }
        }
        __syncthreads();
    }

#pragma unroll
    for (int i = 0; i < 8; i++) {
        int row = m0 + ty * 8 + i;
        if (row < n) {
            __half* hrow = &g_h16[(size_t)row * OUT_DIM];
#pragma unroll
            for (int j = 0; j < 4; j++)
                hrow[tx + 16 * j] = __float2half_rn(acc[i][j]);
            float sv = acc[i][4];
            if (tx < 4)      g_ssrc[row * NH + tx]       = sv;
            else if (tx < 8) g_sdst[row * NH + (tx - 4)] = sv;
        }
    }
}

// ---------------- K1: hist blocks + gemm part A --------------------------
__global__ __launch_bounds__(256, 2) void k1_hist_gemm(const float* __restrict__ x,
                                                       const float* __restrict__ W,
                                                       const int* __restrict__ dst,
                                                       int n, int e) {
    if (blockIdx.x < HIST_BLOCKS) {
        const int stride = HIST_BLOCKS * 256;
        for (int i = blockIdx.x * 256 + threadIdx.x; i < e; i += stride)
            atomicAdd(&g_deg[__ldg(&dst[i])], 1);
        return;
    }
    gemm_body(x, W, (blockIdx.x - HIST_BLOCKS) * 128, n);
}

// ---------------- K_scan: single-kernel exclusive scan (one wave) --------
__global__ __launch_bounds__(1024) void k_scan(int n, int e) {
    __shared__ int warp_sums[32];
    __shared__ int sh_last;
    __shared__ int sh_total;

    int b = blockIdx.x, t = threadIdx.x;
    int i = b * 1024 + t;
    int lane = t & 31, wid = t >> 5;

    int v = (i < n) ? g_deg[i] : 0;
    int s = v;
#pragma unroll
    for (int o = 1; o < 32; o <<= 1) {
        int u = __shfl_up_sync(0xFFFFFFFFu, s, o);
        if (lane >= o) s += u;
    }
    if (lane == 31) warp_sums[wid] = s;
    __syncthreads();
    if (wid == 0) {
        int wsv = warp_sums[lane];
#pragma unroll
        for (int o = 1; o < 32; o <<= 1) {
            int u = __shfl_up_sync(0xFFFFFFFFu, wsv, o);
            if (lane >= o) wsv += u;
        }
        warp_sums[lane] = wsv;
    }
    __syncthreads();
    int woff = wid ? warp_sums[wid - 1] : 0;
    int incl = s + woff;
    int lexcl = incl - v;

    if (t == 1023) sh_total = incl;
    __syncthreads();
    if (t == 0) {
        g_bsum[b] = sh_total;
        __threadfence();
        int old = atomicAdd(&g_count, 1);
        sh_last = (old == gridDim.x - 1) ? 1 : 0;
    }
    __syncthreads();

    if (sh_last) {
        if (t < 32) {
            int base = t * 4;
            int vals[4];
#pragma unroll
            for (int j = 0; j < 4; j++)
                vals[j] = (base + j < (int)gridDim.x) ? g_bsum[base + j] : 0;
            int loc = vals[0] + vals[1] + vals[2] + vals[3];
            int sc = loc;
#pragma unroll
            for (int o = 1; o < 32; o <<= 1) {
                int u = __shfl_up_sync(0xFFFFFFFFu, sc, o);
                if (lane >= o) sc += u;
            }
            int run = sc - loc;
#pragma unroll
            for (int j = 0; j < 4; j++) {
                if (base + j < (int)gridDim.x) g_boff[base + j] = run;
                run += vals[j];
            }
            __threadfence();
            if (t == 0) atomicExch(&g_flag, 1);
        }
    }
    if (t == 0) {
        while (atomicAdd(&g_flag, 0) == 0) { __nanosleep(100); }
    }
    __syncthreads();

    int boff = g_boff[b];
    if (i < n) {
        int r = lexcl + boff;
        g_rowptr[i] = r;
        g_wpos[i]   = r;
    }
    if (i == 0) g_rowptr[n] = e;
}

// ---------------- K2: reorder blocks + gemm part B -----------------------
__global__ __launch_bounds__(256, 2) void k2_reord_gemm(const float* __restrict__ x,
                                                        const float* __restrict__ W,
                                                        const int* __restrict__ src,
                                                        const int* __restrict__ dst,
                                                        int n, int e, int m_base) {
    if (blockIdx.x < REORD_BLOCKS) {
        const int stride = REORD_BLOCKS * 256;
        for (int i = blockIdx.x * 256 + threadIdx.x; i < e; i += stride) {
            int d = __ldg(&dst[i]);
            int p = atomicAdd(&g_wpos[d], 1);
            g_csr[p] = __ldg(&src[i]);
        }
        return;
    }
    gemm_body(x, W, m_base + (blockIdx.x - REORD_BLOCKS) * 128, n);
}

// ---------------- K_agg: fused softmax + fp16-gather aggregation ---------
__global__ __launch_bounds__(256) void k_agg(float* __restrict__ out, int n) {
    int w = (blockIdx.x * blockDim.x + threadIdx.x) >> 5;
    if (w >= n) return;
    int lane = threadIdx.x & 31;
    int slot = lane >> 4;
    int q    = lane & 15;
    int hd   = q >> 2;

    int start = g_rowptr[w];
    int end   = g_rowptr[w + 1];
    float sdst = g_sdst[w * NH + hd];

    float4 acc = make_float4(0.f, 0.f, 0.f, 0.f);
    float ssum = 0.f;

    int j = start + slot;
    int src_cur = (j < end) ? __ldg(&g_csr[j]) : 0;
    for (; j < end; j += 2) {
        int jn = j + 2;
        int src_nxt = (jn < end) ? __ldg(&g_csr[jn]) : 0;   // prefetch
        int src = src_cur;
        float s = __ldg(&g_ssrc[src * NH + hd]) + sdst;
        float ev = (s > 0.f) ? s : 0.2f * s;       // leaky_relu(0.2)
        float p = fast_exp(ev);                    // unshifted exp: max cancels

        union { uint2 u; __half2 h[2]; } cv;
        cv.u = *(const uint2*)&g_h16[(size_t)src * OUT_DIM + q * 4];
        float2 f0 = __half22float2(cv.h[0]);
        float2 f1 = __half22float2(cv.h[1]);

        acc.x = fmaf(p, f0.x, acc.x);
        acc.y = fmaf(p, f0.y, acc.y);
        acc.z = fmaf(p, f1.x, acc.z);
        acc.w = fmaf(p, f1.y, acc.w);
        ssum += p;
        src_cur = src_nxt;
    }

    acc.x += __shfl_xor_sync(0xFFFFFFFFu, acc.x, 16);
    acc.y += __shfl_xor_sync(0xFFFFFFFFu, acc.y, 16);
    acc.z += __shfl_xor_sync(0xFFFFFFFFu, acc.z, 16);
    acc.w += __shfl_xor_sync(0xFFFFFFFFu, acc.w, 16);
    ssum  += __shfl_xor_sync(0xFFFFFFFFu, ssum, 16);

    if (slot == 0) {
        float inv = 1.f / fmaxf(ssum, 1e-9f);
        float4 o = make_float4(acc.x * inv, acc.y * inv, acc.z * inv, acc.w * inv);
        *(float4*)&out[(size_t)w * OUT_DIM + q * 4] = o;
    }
}

// ---------------- launch ---------------------------------------------------
extern "C" void kernel_launch(void* const* d_in, const int* in_sizes, int n_in,
                              void* d_out, int out_size) {
    const float* x     = (const float*)d_in[0];
    const float* W     = (const float*)d_in[1];
    const float* a_src = (const float*)d_in[2];
    const float* a_dst = (const float*)d_in[3];
    const int*   ei    = (const int*)d_in[4];

    int n = in_sizes[0] / IN_DIM;
    int e = in_sizes[4] / 2;
    const int* srcp = ei;
    const int* dstp = ei + e;
    float* out = (float*)d_out;

    int gemm_total = (n + 127) / 128;
    int ga = (gemm_total * 3) / 5;           // ~60% of rows in k1
    int gb = gemm_total - ga;
    int nb = (n + 1023) / 1024;              // <=98 blocks, one wave

    k_prep       <<<(1024 + n + 255) / 256, 256>>>(W, a_src, a_dst, n);
    k1_hist_gemm <<<HIST_BLOCKS + ga, 256>>>(x, W, dstp, n, e);
    k_scan       <<<nb, 1024>>>(n, e);
    k2_reord_gemm<<<REORD_BLOCKS + gb, 256>>>(x, W, srcp, dstp, n, e, ga * 128);
    k_agg        <<<(n + 7) / 8, 256>>>(out, n);
}

// round 15
// speedup vs baseline: 1.2362x; 1.2362x over previous
#include <cuda_runtime.h>
#include <cuda_fp16.h>
#include <stdint.h>

#define IN_DIM 128
#define OUT_DIM 64
#define NH 4
#define DH 16
#define N_MAX 100000
#define E_MAX 1600000

#define HIST_BLOCKS 128
#define REORD_BLOCKS 128

#define KCH 32              // k-chunk
#define KP  36              // padded k stride (floats)

// ---------------- device scratch (no allocations allowed) ----------------
__device__ float  g_va[8 * IN_DIM];                   // rows 0-3 Wt*a_src, 4-7 Wt*a_dst
__device__ __half g_h16[(size_t)N_MAX * OUT_DIM];     // projected features (fp16)
__device__ float  g_ssrc[N_MAX * NH];
__device__ float  g_sdst[N_MAX * NH];
__device__ int    g_deg[N_MAX];
__device__ int    g_rowptr[N_MAX + 1];
__device__ int    g_wpos[N_MAX];
__device__ int    g_csr[E_MAX];
__device__ int    g_bsum[128];
__device__ int    g_boff[128];
__device__ int    g_count;
__device__ int    g_flag;

// ---------------- helpers --------------------------------------------------
__device__ __forceinline__ float fast_exp(float x) {
    float t = x * 1.4426950408889634f;
    float n = rintf(t);
    float u = t - n;
    float p = 1.33335581464e-3f;
    p = fmaf(p, u, 9.61812910763e-3f);
    p = fmaf(p, u, 5.55041086648e-2f);
    p = fmaf(p, u, 2.40226506959e-1f);
    p = fmaf(p, u, 6.93147180560e-1f);
    p = fmaf(p, u, 1.0f);
    int ni = (int)n;
    return __int_as_float(__float_as_int(p) + (ni << 23));
}

// tf32 round: cvt.rna.tf32.f32 requires a .b32 destination operand.
__device__ __forceinline__ float f2tf(float f) {
    uint32_t r;
    asm("cvt.rna.tf32.f32 %0, %1;" : "=r"(r) : "f"(f));
    return __uint_as_float(r);
}
__device__ __forceinline__ float4 f2tf4(float4 v) {
    return make_float4(f2tf(v.x), f2tf(v.y), f2tf(v.z), f2tf(v.w));
}

// ---------------- K_prep: va = W^T a, zero deg, reset scan sync ----------
__global__ void k_prep(const float* __restrict__ W,
                       const float* __restrict__ a_src,
                       const float* __restrict__ a_dst, int n) {
    int idx = blockIdx.x * blockDim.x + threadIdx.x;
    if (idx == 0) { g_count = 0; g_flag = 0; }
    if (idx < 1024) {
        int r = idx >> 7;          // 0..7
        int k = idx & 127;
        int hd = r & 3;
        const float* a = (r < 4) ? a_src : a_dst;
        float s = 0.f;
#pragma unroll
        for (int d = 0; d < DH; d++)
            s = fmaf(W[(hd * DH + d) * IN_DIM + k], a[hd * DH + d], s);
        g_va[r * IN_DIM + k] = s;
    } else if (idx - 1024 < n) {
        g_deg[idx - 1024] = 0;
    }
}

// ---------------- GEMM body: tf32 mma.sync, 128 rows x 72 cols -----------
// 8 warps; warp w owns rows m0+16w..+15. 9 n-tiles of 8 cols (72 = 64 h +
// 8 score). A frag from xs[m][k], B frag from ws[col][k] (col-major B).
__device__ __forceinline__ void gemm_body(const float* __restrict__ x,
                                          const float* __restrict__ W,
                                          int m0, int n) {
    __shared__ __align__(16) float xs[128][KP];   // [m][k-chunk] (tf32 vals)
    __shared__ __align__(16) float ws[72][KP];    // [col][k-chunk]

    const int t    = threadIdx.x;
    const int lane = t & 31;
    const int wid  = t >> 5;          // 0..7
    const int g    = lane >> 2;       // groupID 0..7
    const int tig  = lane & 3;        // threadID_in_group

    float c0[9], c1[9], c2[9], c3[9];
#pragma unroll
    for (int j = 0; j < 9; j++) { c0[j] = 0.f; c1[j] = 0.f; c2[j] = 0.f; c3[j] = 0.f; }

    for (int kk = 0; kk < IN_DIM; kk += KCH) {
        // stage x: 128 rows x 8 float4 (1024 float4), cvt to tf32
#pragma unroll
        for (int i = 0; i < 4; i++) {
            int idx = t + i * 256;
            int r = idx >> 3, cc = idx & 7;
            float4 v = make_float4(0.f, 0.f, 0.f, 0.f);
            if (m0 + r < n)
                v = f2tf4(*(const float4*)&x[(size_t)(m0 + r) * IN_DIM + kk + cc * 4]);
            *(float4*)&xs[r][cc * 4] = v;
        }
        // stage W|va: 72 rows x 8 float4 (576 float4)
#pragma unroll
        for (int i = 0; i < 3; i++) {
            int idx = t + i * 256;
            if (idx < 576) {
                int row = idx >> 3, cc = idx & 7;
                float4 v;
                if (row < 64) v = *(const float4*)&W[row * IN_DIM + kk + cc * 4];
                else          v = *(const float4*)&g_va[(row - 64) * IN_DIM + kk + cc * 4];
                *(float4*)&ws[row][cc * 4] = f2tf4(v);
            }
        }
        __syncthreads();

#pragma unroll
        for (int kc = 0; kc < KCH; kc += 8) {
            const float* xb = &xs[wid * 16 + g][kc + tig];
            uint32_t A0 = __float_as_uint(xb[0]);
            uint32_t A1 = __float_as_uint(xb[8 * KP]);
            uint32_t A2 = __float_as_uint(xb[4]);
            uint32_t A3 = __float_as_uint(xb[8 * KP + 4]);
#pragma unroll
            for (int j = 0; j < 9; j++) {
                const float* bb = &ws[j * 8 + g][kc + tig];
                uint32_t B0 = __float_as_uint(bb[0]);
                uint32_t B1 = __float_as_uint(bb[4]);
                asm volatile(
                    "mma.sync.aligned.m16n8k8.row.col.f32.tf32.tf32.f32 "
                    "{%0,%1,%2,%3}, {%4,%5,%6,%7}, {%8,%9}, {%0,%1,%2,%3};"
                    : "+f"(c0[j]), "+f"(c1[j]), "+f"(c2[j]), "+f"(c3[j])
                    : "r"(A0), "r"(A1), "r"(A2), "r"(A3), "r"(B0), "r"(B1));
            }
        }
        __syncthreads();
    }

    // epilogue: c0/c1 -> row g, c2/c3 -> row g+8; cols = j*8 + 2*tig (+1)
    int r0 = m0 + wid * 16 + g;
    int r1 = r0 + 8;
    bool v0 = (r0 < n), v1 = (r1 < n);
#pragma unroll
    for (int j = 0; j < 8; j++) {
        int col = j * 8 + 2 * tig;
        if (v0) *(__half2*)&g_h16[(size_t)r0 * OUT_DIM + col] =
            __floats2half2_rn(c0[j], c1[j]);
        if (v1) *(__half2*)&g_h16[(size_t)r1 * OUT_DIM + col] =
            __floats2half2_rn(c2[j], c3[j]);
    }
    {   // j = 8: score columns 64..71 -> ssrc (64-67), sdst (68-71)
        int cc = 2 * tig;             // 0,2,4,6
        if (cc < 4) {
            if (v0) { g_ssrc[r0 * NH + cc] = c0[8]; g_ssrc[r0 * NH + cc + 1] = c1[8]; }
            if (v1) { g_ssrc[r1 * NH + cc] = c2[8]; g_ssrc[r1 * NH + cc + 1] = c3[8]; }
        } else {
            int d = cc - 4;
            if (v0) { g_sdst[r0 * NH + d] = c0[8]; g_sdst[r0 * NH + d + 1] = c1[8]; }
            if (v1) { g_sdst[r1 * NH + d] = c2[8]; g_sdst[r1 * NH + d + 1] = c3[8]; }
        }
    }
}

// ---------------- K1: hist blocks + gemm part A --------------------------
__global__ __launch_bounds__(256, 2) void k1_hist_gemm(const float* __restrict__ x,
                                                       const float* __restrict__ W,
                                                       const int* __restrict__ dst,
                                                       int n, int e) {
    if (blockIdx.x < HIST_BLOCKS) {
        const int stride = HIST_BLOCKS * 256;
        for (int i = blockIdx.x * 256 + threadIdx.x; i < e; i += stride)
            atomicAdd(&g_deg[__ldg(&dst[i])], 1);
        return;
    }
    gemm_body(x, W, (blockIdx.x - HIST_BLOCKS) * 128, n);
}

// ---------------- K_scan: single-kernel exclusive scan (one wave) --------
__global__ __launch_bounds__(1024) void k_scan(int n, int e) {
    __shared__ int warp_sums[32];
    __shared__ int sh_last;
    __shared__ int sh_total;

    int b = blockIdx.x, t = threadIdx.x;
    int i = b * 1024 + t;
    int lane = t & 31, wid = t >> 5;

    int v = (i < n) ? g_deg[i] : 0;
    int s = v;
#pragma unroll
    for (int o = 1; o < 32; o <<= 1) {
        int u = __shfl_up_sync(0xFFFFFFFFu, s, o);
        if (lane >= o) s += u;
    }
    if (lane == 31) warp_sums[wid] = s;
    __syncthreads();
    if (wid == 0) {
        int wsv = warp_sums[lane];
#pragma unroll
        for (int o = 1; o < 32; o <<= 1) {
            int u = __shfl_up_sync(0xFFFFFFFFu, wsv, o);
            if (lane >= o) wsv += u;
        }
        warp_sums[lane] = wsv;
    }
    __syncthreads();
    int woff = wid ? warp_sums[wid - 1] : 0;
    int incl = s + woff;
    int lexcl = incl - v;

    if (t == 1023) sh_total = incl;
    __syncthreads();
    if (t == 0) {
        g_bsum[b] = sh_total;
        __threadfence();
        int old = atomicAdd(&g_count, 1);
        sh_last = (old == gridDim.x - 1) ? 1 : 0;
    }
    __syncthreads();

    if (sh_last) {
        if (t < 32) {
            int base = t * 4;
            int vals[4];
#pragma unroll
            for (int j = 0; j < 4; j++)
                vals[j] = (base + j < (int)gridDim.x) ? g_bsum[base + j] : 0;
            int loc = vals[0] + vals[1] + vals[2] + vals[3];
            int sc = loc;
#pragma unroll
            for (int o = 1; o < 32; o <<= 1) {
                int u = __shfl_up_sync(0xFFFFFFFFu, sc, o);
                if (lane >= o) sc += u;
            }
            int run = sc - loc;
#pragma unroll
            for (int j = 0; j < 4; j++) {
                if (base + j < (int)gridDim.x) g_boff[base + j] = run;
                run += vals[j];
            }
            __threadfence();
            if (t == 0) atomicExch(&g_flag, 1);
        }
    }
    if (t == 0) {
        while (atomicAdd(&g_flag, 0) == 0) { __nanosleep(100); }
    }
    __syncthreads();

    int boff = g_boff[b];
    if (i < n) {
        int r = lexcl + boff;
        g_rowptr[i] = r;
        g_wpos[i]   = r;
    }
    if (i == 0) g_rowptr[n] = e;
}

// ---------------- K2: reorder blocks + gemm part B -----------------------
__global__ __launch_bounds__(256, 2) void k2_reord_gemm(const float* __restrict__ x,
                                                        const float* __restrict__ W,
                                                        const int* __restrict__ src,
                                                        const int* __restrict__ dst,
                                                        int n, int e, int m_base) {
    if (blockIdx.x < REORD_BLOCKS) {
        const int stride = REORD_BLOCKS * 256;
        for (int i = blockIdx.x * 256 + threadIdx.x; i < e; i += stride) {
            int d = __ldg(&dst[i]);
            int p = atomicAdd(&g_wpos[d], 1);
            g_csr[p] = __ldg(&src[i]);
        }
        return;
    }
    gemm_body(x, W, m_base + (blockIdx.x - REORD_BLOCKS) * 128, n);
}

// ---------------- K_agg: fused softmax + fp16-gather aggregation ---------
__global__ __launch_bounds__(256) void k_agg(float* __restrict__ out, int n) {
    int w = (blockIdx.x * blockDim.x + threadIdx.x) >> 5;
    if (w >= n) return;
    int lane = threadIdx.x & 31;
    int slot = lane >> 4;
    int q    = lane & 15;
    int hd   = q >> 2;

    int start = g_rowptr[w];
    int end   = g_rowptr[w + 1];
    float sdst = g_sdst[w * NH + hd];

    float4 acc = make_float4(0.f, 0.f, 0.f, 0.f);
    float ssum = 0.f;

    int j = start + slot;
    int src_cur = (j < end) ? __ldg(&g_csr[j]) : 0;
    for (; j < end; j += 2) {
        int jn = j + 2;
        int src_nxt = (jn < end) ? __ldg(&g_csr[jn]) : 0;   // prefetch
        int src = src_cur;
        float s = __ldg(&g_ssrc[src * NH + hd]) + sdst;
        float ev = (s > 0.f) ? s : 0.2f * s;       // leaky_relu(0.2)
        float p = fast_exp(ev);                    // unshifted exp: max cancels

        union { uint2 u; __half2 h[2]; } cv;
        cv.u = *(const uint2*)&g_h16[(size_t)src * OUT_DIM + q * 4];
        float2 f0 = __half22float2(cv.h[0]);
        float2 f1 = __half22float2(cv.h[1]);

        acc.x = fmaf(p, f0.x, acc.x);
        acc.y = fmaf(p, f0.y, acc.y);
        acc.z = fmaf(p, f1.x, acc.z);
        acc.w = fmaf(p, f1.y, acc.w);
        ssum += p;
        src_cur = src_nxt;
    }

    acc.x += __shfl_xor_sync(0xFFFFFFFFu, acc.x, 16);
    acc.y += __shfl_xor_sync(0xFFFFFFFFu, acc.y, 16);
    acc.z += __shfl_xor_sync(0xFFFFFFFFu, acc.z, 16);
    acc.w += __shfl_xor_sync(0xFFFFFFFFu, acc.w, 16);
    ssum  += __shfl_xor_sync(0xFFFFFFFFu, ssum, 16);

    if (slot == 0) {
        float inv = 1.f / fmaxf(ssum, 1e-9f);
        float4 o = make_float4(acc.x * inv, acc.y * inv, acc.z * inv, acc.w * inv);
        *(float4*)&out[(size_t)w * OUT_DIM + q * 4] = o;
    }
}

// ---------------- launch ---------------------------------------------------
extern "C" void kernel_launch(void* const* d_in, const int* in_sizes, int n_in,
                              void* d_out, int out_size) {
    const float* x     = (const float*)d_in[0];
    const float* W     = (const float*)d_in[1];
    const float* a_src = (const float*)d_in[2];
    const float* a_dst = (const float*)d_in[3];
    const int*   ei    = (const int*)d_in[4];

    int n = in_sizes[0] / IN_DIM;
    int e = in_sizes[4] / 2;
    const int* srcp = ei;
    const int* dstp = ei + e;
    float* out = (float*)d_out;

    int gemm_total = (n + 127) / 128;
    int ga = (gemm_total * 3) / 5;           // ~60% of rows in k1
    int gb = gemm_total - ga;
    int nb = (n + 1023) / 1024;              // <=98 blocks, one wave

    k_prep       <<<(1024 + n + 255) / 256, 256>>>(W, a_src, a_dst, n);
    k1_hist_gemm <<<HIST_BLOCKS + ga, 256>>>(x, W, dstp, n, e);
    k_scan       <<<nb, 1024>>>(n, e);
    k2_reord_gemm<<<REORD_BLOCKS + gb, 256>>>(x, W, srcp, dstp, n, e, ga * 128);
    k_agg        <<<(n + 7) / 8, 256>>>(out, n);
}

// round 16
// speedup vs baseline: 1.2952x; 1.0477x over previous
#include <cuda_runtime.h>
#include <cuda_fp16.h>
#include <stdint.h>

#define IN_DIM 128
#define OUT_DIM 64
#define NH 4
#define DH 16
#define N_MAX 100000
#define E_MAX 1600000

#define HIST_BLOCKS 128
#define REORD_BLOCKS 192

#define KCH 32              // k-chunk
#define KP  36              // padded k stride (floats)

// ---------------- device scratch (no allocations allowed) ----------------
__device__ float  g_va[8 * IN_DIM];                   // rows 0-3 Wt*a_src, 4-7 Wt*a_dst
__device__ __half g_h16[(size_t)N_MAX * OUT_DIM];     // projected features (fp16)
__device__ float  g_ssrc[N_MAX * NH];
__device__ float  g_sdst[N_MAX * NH];
__device__ int    g_deg[N_MAX];
__device__ int    g_rowptr[N_MAX + 1];
__device__ int    g_wpos[N_MAX];
__device__ int    g_csr[E_MAX];
__device__ int    g_bsum[128];
__device__ int    g_boff[128];
__device__ int    g_count;
__device__ int    g_flag;

// ---------------- helpers --------------------------------------------------
__device__ __forceinline__ float fast_exp(float x) {
    float t = x * 1.4426950408889634f;
    float n = rintf(t);
    float u = t - n;
    float p = 1.33335581464e-3f;
    p = fmaf(p, u, 9.61812910763e-3f);
    p = fmaf(p, u, 5.55041086648e-2f);
    p = fmaf(p, u, 2.40226506959e-1f);
    p = fmaf(p, u, 6.93147180560e-1f);
    p = fmaf(p, u, 1.0f);
    int ni = (int)n;
    return __int_as_float(__float_as_int(p) + (ni << 23));
}

// tf32 round: cvt.rna.tf32.f32 requires a .b32 destination operand.
__device__ __forceinline__ float f2tf(float f) {
    uint32_t r;
    asm("cvt.rna.tf32.f32 %0, %1;" : "=r"(r) : "f"(f));
    return __uint_as_float(r);
}
__device__ __forceinline__ float4 f2tf4(float4 v) {
    return make_float4(f2tf(v.x), f2tf(v.y), f2tf(v.z), f2tf(v.w));
}

// ---------------- K_prep: va = W^T a, zero deg, reset scan sync ----------
__global__ void k_prep(const float* __restrict__ W,
                       const float* __restrict__ a_src,
                       const float* __restrict__ a_dst, int n) {
    int idx = blockIdx.x * blockDim.x + threadIdx.x;
    if (idx == 0) { g_count = 0; g_flag = 0; }
    if (idx < 1024) {
        int r = idx >> 7;          // 0..7
        int k = idx & 127;
        int hd = r & 3;
        const float* a = (r < 4) ? a_src : a_dst;
        float s = 0.f;
#pragma unroll
        for (int d = 0; d < DH; d++)
            s = fmaf(W[(hd * DH + d) * IN_DIM + k], a[hd * DH + d], s);
        g_va[r * IN_DIM + k] = s;
    } else if (idx - 1024 < n) {
        g_deg[idx - 1024] = 0;
    }
}

// ---------------- GEMM body: tf32 mma.sync, 128 rows x 72 cols -----------
__device__ __forceinline__ void gemm_body(const float* __restrict__ x,
                                          const float* __restrict__ W,
                                          int m0, int n) {
    __shared__ __align__(16) float xs[128][KP];   // [m][k-chunk] (tf32 vals)
    __shared__ __align__(16) float ws[72][KP];    // [col][k-chunk]

    const int t    = threadIdx.x;
    const int lane = t & 31;
    const int wid  = t >> 5;          // 0..7
    const int g    = lane >> 2;       // groupID 0..7
    const int tig  = lane & 3;        // threadID_in_group

    float c0[9], c1[9], c2[9], c3[9];
#pragma unroll
    for (int j = 0; j < 9; j++) { c0[j] = 0.f; c1[j] = 0.f; c2[j] = 0.f; c3[j] = 0.f; }

    for (int kk = 0; kk < IN_DIM; kk += KCH) {
#pragma unroll
        for (int i = 0; i < 4; i++) {
            int idx = t + i * 256;
            int r = idx >> 3, cc = idx & 7;
            float4 v = make_float4(0.f, 0.f, 0.f, 0.f);
            if (m0 + r < n)
                v = f2tf4(*(const float4*)&x[(size_t)(m0 + r) * IN_DIM + kk + cc * 4]);
            *(float4*)&xs[r][cc * 4] = v;
        }
#pragma unroll
        for (int i = 0; i < 3; i++) {
            int idx = t + i * 256;
            if (idx < 576) {
                int row = idx >> 3, cc = idx & 7;
                float4 v;
                if (row < 64) v = *(const float4*)&W[row * IN_DIM + kk + cc * 4];
                else          v = *(const float4*)&g_va[(row - 64) * IN_DIM + kk + cc * 4];
                *(float4*)&ws[row][cc * 4] = f2tf4(v);
            }
        }
        __syncthreads();

#pragma unroll
        for (int kc = 0; kc < KCH; kc += 8) {
            const float* xb = &xs[wid * 16 + g][kc + tig];
            uint32_t A0 = __float_as_uint(xb[0]);
            uint32_t A1 = __float_as_uint(xb[8 * KP]);
            uint32_t A2 = __float_as_uint(xb[4]);
            uint32_t A3 = __float_as_uint(xb[8 * KP + 4]);
#pragma unroll
            for (int j = 0; j < 9; j++) {
                const float* bb = &ws[j * 8 + g][kc + tig];
                uint32_t B0 = __float_as_uint(bb[0]);
                uint32_t B1 = __float_as_uint(bb[4]);
                asm volatile(
                    "mma.sync.aligned.m16n8k8.row.col.f32.tf32.tf32.f32 "
                    "{%0,%1,%2,%3}, {%4,%5,%6,%7}, {%8,%9}, {%0,%1,%2,%3};"
                    : "+f"(c0[j]), "+f"(c1[j]), "+f"(c2[j]), "+f"(c3[j])
                    : "r"(A0), "r"(A1), "r"(A2), "r"(A3), "r"(B0), "r"(B1));
            }
        }
        __syncthreads();
    }

    int r0 = m0 + wid * 16 + g;
    int r1 = r0 + 8;
    bool v0 = (r0 < n), v1 = (r1 < n);
#pragma unroll
    for (int j = 0; j < 8; j++) {
        int col = j * 8 + 2 * tig;
        if (v0) *(__half2*)&g_h16[(size_t)r0 * OUT_DIM + col] =
            __floats2half2_rn(c0[j], c1[j]);
        if (v1) *(__half2*)&g_h16[(size_t)r1 * OUT_DIM + col] =
            __floats2half2_rn(c2[j], c3[j]);
    }
    {   // score columns 64..71 -> ssrc (64-67), sdst (68-71)
        int cc = 2 * tig;             // 0,2,4,6
        if (cc < 4) {
            if (v0) { g_ssrc[r0 * NH + cc] = c0[8]; g_ssrc[r0 * NH + cc + 1] = c1[8]; }
            if (v1) { g_ssrc[r1 * NH + cc] = c2[8]; g_ssrc[r1 * NH + cc + 1] = c3[8]; }
        } else {
            int d = cc - 4;
            if (v0) { g_sdst[r0 * NH + d] = c0[8]; g_sdst[r0 * NH + d + 1] = c1[8]; }
            if (v1) { g_sdst[r1 * NH + d] = c2[8]; g_sdst[r1 * NH + d + 1] = c3[8]; }
        }
    }
}

// ---------------- K1: hist blocks (MLP-4) + gemm part A ------------------
__global__ __launch_bounds__(256, 2) void k1_hist_gemm(const float* __restrict__ x,
                                                       const float* __restrict__ W,
                                                       const int* __restrict__ dst,
                                                       int n, int e) {
    if (blockIdx.x < HIST_BLOCKS) {
        const int stride = HIST_BLOCKS * 256;
        int i = blockIdx.x * 256 + threadIdx.x;
        for (; i + 3 * stride < e; i += 4 * stride) {
            int d0 = __ldg(&dst[i]);
            int d1 = __ldg(&dst[i + stride]);
            int d2 = __ldg(&dst[i + 2 * stride]);
            int d3 = __ldg(&dst[i + 3 * stride]);
            atomicAdd(&g_deg[d0], 1);
            atomicAdd(&g_deg[d1], 1);
            atomicAdd(&g_deg[d2], 1);
            atomicAdd(&g_deg[d3], 1);
        }
        for (; i < e; i += stride)
            atomicAdd(&g_deg[__ldg(&dst[i])], 1);
        return;
    }
    gemm_body(x, W, (blockIdx.x - HIST_BLOCKS) * 128, n);
}

// ---------------- K_scan: single-kernel exclusive scan (one wave) --------
__global__ __launch_bounds__(1024) void k_scan(int n, int e) {
    __shared__ int warp_sums[32];
    __shared__ int sh_last;
    __shared__ int sh_total;

    int b = blockIdx.x, t = threadIdx.x;
    int i = b * 1024 + t;
    int lane = t & 31, wid = t >> 5;

    int v = (i < n) ? g_deg[i] : 0;
    int s = v;
#pragma unroll
    for (int o = 1; o < 32; o <<= 1) {
        int u = __shfl_up_sync(0xFFFFFFFFu, s, o);
        if (lane >= o) s += u;
    }
    if (lane == 31) warp_sums[wid] = s;
    __syncthreads();
    if (wid == 0) {
        int wsv = warp_sums[lane];
#pragma unroll
        for (int o = 1; o < 32; o <<= 1) {
            int u = __shfl_up_sync(0xFFFFFFFFu, wsv, o);
            if (lane >= o) wsv += u;
        }
        warp_sums[lane] = wsv;
    }
    __syncthreads();
    int woff = wid ? warp_sums[wid - 1] : 0;
    int incl = s + woff;
    int lexcl = incl - v;

    if (t == 1023) sh_total = incl;
    __syncthreads();
    if (t == 0) {
        g_bsum[b] = sh_total;
        __threadfence();
        int old = atomicAdd(&g_count, 1);
        sh_last = (old == gridDim.x - 1) ? 1 : 0;
    }
    __syncthreads();

    if (sh_last) {
        if (t < 32) {
            int base = t * 4;
            int vals[4];
#pragma unroll
            for (int j = 0; j < 4; j++)
                vals[j] = (base + j < (int)gridDim.x) ? g_bsum[base + j] : 0;
            int loc = vals[0] + vals[1] + vals[2] + vals[3];
            int sc = loc;
#pragma unroll
            for (int o = 1; o < 32; o <<= 1) {
                int u = __shfl_up_sync(0xFFFFFFFFu, sc, o);
                if (lane >= o) sc += u;
            }
            int run = sc - loc;
#pragma unroll
            for (int j = 0; j < 4; j++) {
                if (base + j < (int)gridDim.x) g_boff[base + j] = run;
                run += vals[j];
            }
            __threadfence();
            if (t == 0) atomicExch(&g_flag, 1);
        }
    }
    if (t == 0) {
        while (atomicAdd(&g_flag, 0) == 0) { __nanosleep(100); }
    }
    __syncthreads();

    int boff = g_boff[b];
    if (i < n) {
        int r = lexcl + boff;
        g_rowptr[i] = r;
        g_wpos[i]   = r;
    }
    if (i == 0) g_rowptr[n] = e;
}

// ---------------- K2: reorder blocks (MLP-4) + gemm part B ---------------
__global__ __launch_bounds__(256, 2) void k2_reord_gemm(const float* __restrict__ x,
                                                        const float* __restrict__ W,
                                                        const int* __restrict__ src,
                                                        const int* __restrict__ dst,
                                                        int n, int e, int m_base) {
    if (blockIdx.x < REORD_BLOCKS) {
        const int stride = REORD_BLOCKS * 256;
        int i = blockIdx.x * 256 + threadIdx.x;
        for (; i + 3 * stride < e; i += 4 * stride) {
            int d0 = __ldg(&dst[i]);
            int d1 = __ldg(&dst[i + stride]);
            int d2 = __ldg(&dst[i + 2 * stride]);
            int d3 = __ldg(&dst[i + 3 * stride]);
            int s0 = __ldg(&src[i]);
            int s1 = __ldg(&src[i + stride]);
            int s2 = __ldg(&src[i + 2 * stride]);
            int s3 = __ldg(&src[i + 3 * stride]);
            int p0 = atomicAdd(&g_wpos[d0], 1);
            int p1 = atomicAdd(&g_wpos[d1], 1);
            int p2 = atomicAdd(&g_wpos[d2], 1);
            int p3 = atomicAdd(&g_wpos[d3], 1);
            g_csr[p0] = s0;
            g_csr[p1] = s1;
            g_csr[p2] = s2;
            g_csr[p3] = s3;
        }
        for (; i < e; i += stride) {
            int d = __ldg(&dst[i]);
            int p = atomicAdd(&g_wpos[d], 1);
            g_csr[p] = __ldg(&src[i]);
        }
        return;
    }
    gemm_body(x, W, m_base + (blockIdx.x - REORD_BLOCKS) * 128, n);
}

// ---------------- K_agg: fused softmax + fp16 gather, 4 edges in flight --
// One warp per dst node. 8 lanes per edge (lane q: cols 8q..8q+7, 16B of
// fp16), 4 edge slots. fp32 accumulation; reduce slots via 2 shfl stages.
__global__ __launch_bounds__(256) void k_agg(float* __restrict__ out, int n) {
    int w = (blockIdx.x * blockDim.x + threadIdx.x) >> 5;
    if (w >= n) return;
    int lane = threadIdx.x & 31;
    int slot = lane >> 3;             // 0..3
    int q    = lane & 7;              // 0..7 -> cols 8q..8q+7
    int hd   = q >> 1;                // 0..3

    int start = g_rowptr[w];
    int end   = g_rowptr[w + 1];
    float sdst = g_sdst[w * NH + hd];

    float acc[8];
#pragma unroll
    for (int c = 0; c < 8; c++) acc[c] = 0.f;
    float ssum = 0.f;

    int j = start + slot;
    int src_cur = (j < end) ? __ldg(&g_csr[j]) : 0;
    for (; j < end; j += 4) {
        int jn = j + 4;
        int src_nxt = (jn < end) ? __ldg(&g_csr[jn]) : 0;   // prefetch
        int src = src_cur;
        float s = __ldg(&g_ssrc[src * NH + hd]) + sdst;
        float ev = (s > 0.f) ? s : 0.2f * s;       // leaky_relu(0.2)
        float p = fast_exp(ev);                    // unshifted exp: max cancels

        union { uint4 u; __half2 h[4]; } cv;
        cv.u = *(const uint4*)&g_h16[(size_t)src * OUT_DIM + q * 8];
#pragma unroll
        for (int c = 0; c < 4; c++) {
            float2 f = __half22float2(cv.h[c]);
            acc[2 * c]     = fmaf(p, f.x, acc[2 * c]);
            acc[2 * c + 1] = fmaf(p, f.y, acc[2 * c + 1]);
        }
        ssum += p;
        src_cur = src_nxt;
    }

    // reduce the 4 edge slots (lanes q, q+8, q+16, q+24)
#pragma unroll
    for (int c = 0; c < 8; c++) {
        acc[c] += __shfl_xor_sync(0xFFFFFFFFu, acc[c], 16);
        acc[c] += __shfl_xor_sync(0xFFFFFFFFu, acc[c], 8);
    }
    ssum += __shfl_xor_sync(0xFFFFFFFFu, ssum, 16);
    ssum += __shfl_xor_sync(0xFFFFFFFFu, ssum, 8);

    if (slot == 0) {
        float inv = 1.f / fmaxf(ssum, 1e-9f);
        float* orow = &out[(size_t)w * OUT_DIM + q * 8];
        float4 o0 = make_float4(acc[0] * inv, acc[1] * inv, acc[2] * inv, acc[3] * inv);
        float4 o1 = make_float4(acc[4] * inv, acc[5] * inv, acc[6] * inv, acc[7] * inv);
        *(float4*)&orow[0] = o0;
        *(float4*)&orow[4] = o1;
    }
}

// ---------------- launch ---------------------------------------------------
extern "C" void kernel_launch(void* const* d_in, const int* in_sizes, int n_in,
                              void* d_out, int out_size) {
    const float* x     = (const float*)d_in[0];
    const float* W     = (const float*)d_in[1];
    const float* a_src = (const float*)d_in[2];
    const float* a_dst = (const float*)d_in[3];
    const int*   ei    = (const int*)d_in[4];

    int n = in_sizes[0] / IN_DIM;
    int e = in_sizes[4] / 2;
    const int* srcp = ei;
    const int* dstp = ei + e;
    float* out = (float*)d_out;

    int gemm_total = (n + 127) / 128;
    int ga = (gemm_total * 3) / 5;           // ~60% of rows in k1
    int gb = gemm_total - ga;
    int nb = (n + 1023) / 1024;              // <=98 blocks, one wave

    k_prep       <<<(1024 + n + 255) / 256, 256>>>(W, a_src, a_dst, n);
    k1_hist_gemm <<<HIST_BLOCKS + ga, 256>>>(x, W, dstp, n, e);
    k_scan       <<<nb, 1024>>>(n, e);
    k2_reord_gemm<<<REORD_BLOCKS + gb, 256>>>(x, W, srcp, dstp, n, e, ga * 128);
    k_agg        <<<(n + 7) / 8, 256>>>(out, n);
}

// round 17
// speedup vs baseline: 1.3658x; 1.0545x over previous
#include <cuda_runtime.h>
#include <cuda_fp16.h>
#include <stdint.h>

#define IN_DIM 128
#define OUT_DIM 64
#define NH 4
#define DH 16
#define N_MAX 100000
#define E_MAX 1600000

#define HIST_BLOCKS 128
#define REORD_BLOCKS 192

#define KC2 16              // k-chunk (pipelined)
#define KP2 20              // padded k stride (floats)
#define NCHUNK (IN_DIM / KC2)

// ---------------- device scratch (no allocations allowed) ----------------
__device__ float  g_va[8 * IN_DIM];                   // rows 0-3 Wt*a_src, 4-7 Wt*a_dst
__device__ __half g_h16[(size_t)N_MAX * OUT_DIM];     // projected features (fp16)
__device__ float  g_ssrc[N_MAX * NH];
__device__ float  g_sdst[N_MAX * NH];
__device__ int    g_deg[N_MAX];
__device__ int    g_rowptr[N_MAX + 1];
__device__ int    g_wpos[N_MAX];
__device__ int    g_csr[E_MAX];
__device__ int    g_bsum[128];
__device__ int    g_boff[128];
__device__ int    g_count;
__device__ int    g_flag;

// ---------------- helpers --------------------------------------------------
__device__ __forceinline__ float fast_exp(float x) {
    float t = x * 1.4426950408889634f;
    float n = rintf(t);
    float u = t - n;
    float p = 1.33335581464e-3f;
    p = fmaf(p, u, 9.61812910763e-3f);
    p = fmaf(p, u, 5.55041086648e-2f);
    p = fmaf(p, u, 2.40226506959e-1f);
    p = fmaf(p, u, 6.93147180560e-1f);
    p = fmaf(p, u, 1.0f);
    int ni = (int)n;
    return __int_as_float(__float_as_int(p) + (ni << 23));
}

#define CP_A16(sm, gp, sz) \
    asm volatile("cp.async.cg.shared.global [%0], [%1], 16, %2;" \
                 :: "r"(sm), "l"(gp), "r"(sz))
#define CP_COMMIT() asm volatile("cp.async.commit_group;")
#define CP_WAIT1()  asm volatile("cp.async.wait_group 1;")
#define CP_WAIT0()  asm volatile("cp.async.wait_group 0;")

// ---------------- K_prep: va = W^T a, zero deg, reset scan sync ----------
__global__ void k_prep(const float* __restrict__ W,
                       const float* __restrict__ a_src,
                       const float* __restrict__ a_dst, int n) {
    int idx = blockIdx.x * blockDim.x + threadIdx.x;
    if (idx == 0) { g_count = 0; g_flag = 0; }
    if (idx < 1024) {
        int r = idx >> 7;          // 0..7
        int k = idx & 127;
        int hd = r & 3;
        const float* a = (r < 4) ? a_src : a_dst;
        float s = 0.f;
#pragma unroll
        for (int d = 0; d < DH; d++)
            s = fmaf(W[(hd * DH + d) * IN_DIM + k], a[hd * DH + d], s);
        g_va[r * IN_DIM + k] = s;
    } else if (idx - 1024 < n) {
        g_deg[idx - 1024] = 0;
    }
}

// ---------------- GEMM body: tf32 mma, cp.async 2-stage pipeline ---------
// 128 rows x 72 cols per block. 8 warps; warp w owns rows m0+16w..+15.
// 8 k-chunks of 16, double-buffered via cp.async (staging latency paid once).
// tf32 operands are raw fp32 bits (HW uses top 19 bits).
__device__ __forceinline__ void gemm_body(const float* __restrict__ x,
                                          const float* __restrict__ W,
                                          int m0, int n) {
    __shared__ __align__(16) float xs[2][128][KP2];
    __shared__ __align__(16) float ws[2][72][KP2];

    const int t    = threadIdx.x;
    const int lane = t & 31;
    const int wid  = t >> 5;          // 0..7
    const int g    = lane >> 2;       // groupID 0..7
    const int tig  = lane & 3;        // threadID_in_group

    float c0[9], c1[9], c2[9], c3[9];
#pragma unroll
    for (int j = 0; j < 9; j++) { c0[j] = 0.f; c1[j] = 0.f; c2[j] = 0.f; c3[j] = 0.f; }

    // stage chunk c into buffer buf: 512 x-float4 + 288 w-float4 = 800
    auto stage = [&](int c, int buf) {
        int kk = c * KC2;
#pragma unroll
        for (int i = 0; i < 4; i++) {
            int idx = t + i * 256;
            if (idx < 512) {
                int r = idx >> 2, cc = idx & 3;
                const float* gp = &x[(size_t)(m0 + r) * IN_DIM + kk + cc * 4];
                uint32_t sa = (uint32_t)__cvta_generic_to_shared(&xs[buf][r][cc * 4]);
                int sz = (m0 + r < n) ? 16 : 0;     // zero-fill OOB rows
                CP_A16(sa, gp, sz);
            } else if (idx < 800) {
                int wix = idx - 512;
                int row = wix >> 2, cc = wix & 3;
                const float* gp = (row < 64)
                    ? &W[row * IN_DIM + kk + cc * 4]
                    : &g_va[(row - 64) * IN_DIM + kk + cc * 4];
                uint32_t sa = (uint32_t)__cvta_generic_to_shared(&ws[buf][row][cc * 4]);
                CP_A16(sa, gp, 16);
            }
        }
    };

    stage(0, 0);
    CP_COMMIT();

#pragma unroll
    for (int c = 0; c < NCHUNK; c++) {
        int buf = c & 1;
        if (c < NCHUNK - 1) {
            stage(c + 1, (c + 1) & 1);
            CP_COMMIT();
            CP_WAIT1();                 // chunk c resident
        } else {
            CP_WAIT0();
        }
        __syncthreads();

#pragma unroll
        for (int kc = 0; kc < KC2; kc += 8) {
            const float* xb = &xs[buf][wid * 16 + g][kc + tig];
            uint32_t A0 = __float_as_uint(xb[0]);
            uint32_t A1 = __float_as_uint(xb[8 * KP2]);
            uint32_t A2 = __float_as_uint(xb[4]);
            uint32_t A3 = __float_as_uint(xb[8 * KP2 + 4]);
#pragma unroll
            for (int j = 0; j < 9; j++) {
                const float* bb = &ws[buf][j * 8 + g][kc + tig];
                uint32_t B0 = __float_as_uint(bb[0]);
                uint32_t B1 = __float_as_uint(bb[4]);
                asm volatile(
                    "mma.sync.aligned.m16n8k8.row.col.f32.tf32.tf32.f32 "
                    "{%0,%1,%2,%3}, {%4,%5,%6,%7}, {%8,%9}, {%0,%1,%2,%3};"
                    : "+f"(c0[j]), "+f"(c1[j]), "+f"(c2[j]), "+f"(c3[j])
                    : "r"(A0), "r"(A1), "r"(A2), "r"(A3), "r"(B0), "r"(B1));
            }
        }
        __syncthreads();                // buffer safe to overwrite next iter
    }

    int r0 = m0 + wid * 16 + g;
    int r1 = r0 + 8;
    bool v0 = (r0 < n), v1 = (r1 < n);
#pragma unroll
    for (int j = 0; j < 8; j++) {
        int col = j * 8 + 2 * tig;
        if (v0) *(__half2*)&g_h16[(size_t)r0 * OUT_DIM + col] =
            __floats2half2_rn(c0[j], c1[j]);
        if (v1) *(__half2*)&g_h16[(size_t)r1 * OUT_DIM + col] =
            __floats2half2_rn(c2[j], c3[j]);
    }
    {   // score columns 64..71 -> ssrc (64-67), sdst (68-71)
        int cc = 2 * tig;             // 0,2,4,6
        if (cc < 4) {
            if (v0) { g_ssrc[r0 * NH + cc] = c0[8]; g_ssrc[r0 * NH + cc + 1] = c1[8]; }
            if (v1) { g_ssrc[r1 * NH + cc] = c2[8]; g_ssrc[r1 * NH + cc + 1] = c3[8]; }
        } else {
            int d = cc - 4;
            if (v0) { g_sdst[r0 * NH + d] = c0[8]; g_sdst[r0 * NH + d + 1] = c1[8]; }
            if (v1) { g_sdst[r1 * NH + d] = c2[8]; g_sdst[r1 * NH + d + 1] = c3[8]; }
        }
    }
}

// ---------------- K1: hist blocks (MLP-4) + gemm part A ------------------
__global__ __launch_bounds__(256, 2) void k1_hist_gemm(const float* __restrict__ x,
                                                       const float* __restrict__ W,
                                                       const int* __restrict__ dst,
                                                       int n, int e) {
    if (blockIdx.x < HIST_BLOCKS) {
        const int stride = HIST_BLOCKS * 256;
        int i = blockIdx.x * 256 + threadIdx.x;
        for (; i + 3 * stride < e; i += 4 * stride) {
            int d0 = __ldg(&dst[i]);
            int d1 = __ldg(&dst[i + stride]);
            int d2 = __ldg(&dst[i + 2 * stride]);
            int d3 = __ldg(&dst[i + 3 * stride]);
            atomicAdd(&g_deg[d0], 1);
            atomicAdd(&g_deg[d1], 1);
            atomicAdd(&g_deg[d2], 1);
            atomicAdd(&g_deg[d3], 1);
        }
        for (; i < e; i += stride)
            atomicAdd(&g_deg[__ldg(&dst[i])], 1);
        return;
    }
    gemm_body(x, W, (blockIdx.x - HIST_BLOCKS) * 128, n);
}

// ---------------- K_scan: single-kernel exclusive scan (one wave) --------
__global__ __launch_bounds__(1024) void k_scan(int n, int e) {
    __shared__ int warp_sums[32];
    __shared__ int sh_last;
    __shared__ int sh_total;

    int b = blockIdx.x, t = threadIdx.x;
    int i = b * 1024 + t;
    int lane = t & 31, wid = t >> 5;

    int v = (i < n) ? g_deg[i] : 0;
    int s = v;
#pragma unroll
    for (int o = 1; o < 32; o <<= 1) {
        int u = __shfl_up_sync(0xFFFFFFFFu, s, o);
        if (lane >= o) s += u;
    }
    if (lane == 31) warp_sums[wid] = s;
    __syncthreads();
    if (wid == 0) {
        int wsv = warp_sums[lane];
#pragma unroll
        for (int o = 1; o < 32; o <<= 1) {
            int u = __shfl_up_sync(0xFFFFFFFFu, wsv, o);
            if (lane >= o) wsv += u;
        }
        warp_sums[lane] = wsv;
    }
    __syncthreads();
    int woff = wid ? warp_sums[wid - 1] : 0;
    int incl = s + woff;
    int lexcl = incl - v;

    if (t == 1023) sh_total = incl;
    __syncthreads();
    if (t == 0) {
        g_bsum[b] = sh_total;
        __threadfence();
        int old = atomicAdd(&g_count, 1);
        sh_last = (old == gridDim.x - 1) ? 1 : 0;
    }
    __syncthreads();

    if (sh_last) {
        if (t < 32) {
            int base = t * 4;
            int vals[4];
#pragma unroll
            for (int j = 0; j < 4; j++)
                vals[j] = (base + j < (int)gridDim.x) ? g_bsum[base + j] : 0;
            int loc = vals[0] + vals[1] + vals[2] + vals[3];
            int sc = loc;
#pragma unroll
            for (int o = 1; o < 32; o <<= 1) {
                int u = __shfl_up_sync(0xFFFFFFFFu, sc, o);
                if (lane >= o) sc += u;
            }
            int run = sc - loc;
#pragma unroll
            for (int j = 0; j < 4; j++) {
                if (base + j < (int)gridDim.x) g_boff[base + j] = run;
                run += vals[j];
            }
            __threadfence();
            if (t == 0) atomicExch(&g_flag, 1);
        }
    }
    if (t == 0) {
        while (atomicAdd(&g_flag, 0) == 0) { __nanosleep(100); }
    }
    __syncthreads();

    int boff = g_boff[b];
    if (i < n) {
        int r = lexcl + boff;
        g_rowptr[i] = r;
        g_wpos[i]   = r;
    }
    if (i == 0) g_rowptr[n] = e;
}

// ---------------- K2: reorder blocks (MLP-4) + gemm part B ---------------
__global__ __launch_bounds__(256, 2) void k2_reord_gemm(const float* __restrict__ x,
                                                        const float* __restrict__ W,
                                                        const int* __restrict__ src,
                                                        const int* __restrict__ dst,
                                                        int n, int e, int m_base) {
    if (blockIdx.x < REORD_BLOCKS) {
        const int stride = REORD_BLOCKS * 256;
        int i = blockIdx.x * 256 + threadIdx.x;
        for (; i + 3 * stride < e; i += 4 * stride) {
            int d0 = __ldg(&dst[i]);
            int d1 = __ldg(&dst[i + stride]);
            int d2 = __ldg(&dst[i + 2 * stride]);
            int d3 = __ldg(&dst[i + 3 * stride]);
            int s0 = __ldg(&src[i]);
            int s1 = __ldg(&src[i + stride]);
            int s2 = __ldg(&src[i + 2 * stride]);
            int s3 = __ldg(&src[i + 3 * stride]);
            int p0 = atomicAdd(&g_wpos[d0], 1);
            int p1 = atomicAdd(&g_wpos[d1], 1);
            int p2 = atomicAdd(&g_wpos[d2], 1);
            int p3 = atomicAdd(&g_wpos[d3], 1);
            g_csr[p0] = s0;
            g_csr[p1] = s1;
            g_csr[p2] = s2;
            g_csr[p3] = s3;
        }
        for (; i < e; i += stride) {
            int d = __ldg(&dst[i]);
            int p = atomicAdd(&g_wpos[d], 1);
            g_csr[p] = __ldg(&src[i]);
        }
        return;
    }
    gemm_body(x, W, m_base + (blockIdx.x - REORD_BLOCKS) * 128, n);
}

// ---------------- K_agg: fused softmax + fp16 gather, 4 edges in flight --
__global__ __launch_bounds__(256) void k_agg(float* __restrict__ out, int n) {
    int w = (blockIdx.x * blockDim.x + threadIdx.x) >> 5;
    if (w >= n) return;
    int lane = threadIdx.x & 31;
    int slot = lane >> 3;             // 0..3
    int q    = lane & 7;              // 0..7 -> cols 8q..8q+7
    int hd   = q >> 1;                // 0..3

    int start = g_rowptr[w];
    int end   = g_rowptr[w + 1];
    float sdst = g_sdst[w * NH + hd];

    float acc[8];
#pragma unroll
    for (int c = 0; c < 8; c++) acc[c] = 0.f;
    float ssum = 0.f;

    int j = start + slot;
    int src_cur = (j < end) ? __ldg(&g_csr[j]) : 0;
    for (; j < end; j += 4) {
        int jn = j + 4;
        int src_nxt = (jn < end) ? __ldg(&g_csr[jn]) : 0;   // prefetch
        int src = src_cur;
        float s = __ldg(&g_ssrc[src * NH + hd]) + sdst;
        float ev = (s > 0.f) ? s : 0.2f * s;       // leaky_relu(0.2)
        float p = fast_exp(ev);                    // unshifted exp: max cancels

        union { uint4 u; __half2 h[4]; } cv;
        cv.u = *(const uint4*)&g_h16[(size_t)src * OUT_DIM + q * 8];
#pragma unroll
        for (int c = 0; c < 4; c++) {
            float2 f = __half22float2(cv.h[c]);
            acc[2 * c]     = fmaf(p, f.x, acc[2 * c]);
            acc[2 * c + 1] = fmaf(p, f.y, acc[2 * c + 1]);
        }
        ssum += p;
        src_cur = src_nxt;
    }

#pragma unroll
    for (int c = 0; c < 8; c++) {
        acc[c] += __shfl_xor_sync(0xFFFFFFFFu, acc[c], 16);
        acc[c] += __shfl_xor_sync(0xFFFFFFFFu, acc[c], 8);
    }
    ssum += __shfl_xor_sync(0xFFFFFFFFu, ssum, 16);
    ssum += __shfl_xor_sync(0xFFFFFFFFu, ssum, 8);

    if (slot == 0) {
        float inv = 1.f / fmaxf(ssum, 1e-9f);
        float* orow = &out[(size_t)w * OUT_DIM + q * 8];
        float4 o0 = make_float4(acc[0] * inv, acc[1] * inv, acc[2] * inv, acc[3] * inv);
        float4 o1 = make_float4(acc[4] * inv, acc[5] * inv, acc[6] * inv, acc[7] * inv);
        *(float4*)&orow[0] = o0;
        *(float4*)&orow[4] = o1;
    }
}

// ---------------- launch ---------------------------------------------------
extern "C" void kernel_launch(void* const* d_in, const int* in_sizes, int n_in,
                              void* d_out, int out_size) {
    const float* x     = (const float*)d_in[0];
    const float* W     = (const float*)d_in[1];
    const float* a_src = (const float*)d_in[2];
    const float* a_dst = (const float*)d_in[3];
    const int*   ei    = (const int*)d_in[4];

    int n = in_sizes[0] / IN_DIM;
    int e = in_sizes[4] / 2;
    const int* srcp = ei;
    const int* dstp = ei + e;
    float* out = (float*)d_out;

    int gemm_total = (n + 127) / 128;
    int ga = (gemm_total * 3) / 5;           // ~60% of rows in k1
    int gb = gemm_total - ga;
    int nb = (n + 1023) / 1024;              // <=98 blocks, one wave

    k_prep       <<<(1024 + n + 255) / 256, 256>>>(W, a_src, a_dst, n);
    k1_hist_gemm <<<HIST_BLOCKS + ga, 256>>>(x, W, dstp, n, e);
    k_scan       <<<nb, 1024>>>(n, e);
    k2_reord_gemm<<<REORD_BLOCKS + gb, 256>>>(x, W, srcp, dstp, n, e, ga * 128);
    k_agg        <<<(n + 7) / 8, 256>>>(out, n);
}